// round 11
// baseline (speedup 1.0000x reference)
#include <cuda_runtime.h>

namespace cfg {
constexpr int V = 17;
constexpr int D = 128;
constexpr int H = 256;
constexpr int E = 32;
constexpr float LN_EPS = 1e-5f;
constexpr int PAD = 20;   // 80B rows, 16B-aligned

// ---- per-batch shared block (float offsets, relative to S = sm + b*BSTR) ----
constexpr int HT_OFF  = 0;                 // hT[128][20]
constexpr int R3_OFF  = HT_OFF + D * PAD;  // 2560: hsumT[256][20] / hid2T / XB
constexpr int HST_OFF = R3_OFF;
constexpr int H2T_OFF = R3_OFF;
constexpr int XB_OFF  = R3_OFF;            // x[17][128]
constexpr int R2_OFF  = R3_OFF + H * PAD;  // 7680: Q(4352)/AG(2560)/EP(2176)
constexpr int Q_OFF   = R2_OFF;
constexpr int AG_OFF  = R2_OFF;
constexpr int EP_OFF  = R2_OFF;
constexpr int C2P_OFF = R2_OFF + D * PAD;  // 10240: C2 partials [128][17]
constexpr int MISC    = C2P_OFF + D * V;   // 12416
constexpr int SX_OFF = MISC;
constexpr int SY_OFF = SX_OFF + V;
constexpr int MF_OFF = SY_OFF + V;
constexpr int IV_OFF = MF_OFF + V;
constexpr int HB_OFF = IV_OFF + V;
constexpr int DN_OFF = HB_OFF + V;
constexpr int RX_OFF = DN_OFF + V;
constexpr int RY_OFF = RX_OFF + E;
constexpr int VA_OFF = RY_OFF + E;
constexpr int SRX_OFF = VA_OFF + E;
constexpr int SRY_OFF = SRX_OFF + E;
constexpr int SVA_OFF = SRY_OFF + E;
constexpr int BSTR_RAW = SVA_OFF + E;      // 12710
constexpr int BSTR = (BSTR_RAW + 3) & ~3;  // 12712, 16B-aligned
constexpr int INT_OFF = 2 * BSTR;          // 25424
constexpr int I_DST = 0, I_SRC = 32, I_SSRC = 64, I_EORD = 96, I_CNT = 128, I_OFFA = 145;
constexpr int SMEM_FLOATS = INT_OFF + 164;
constexpr int SMEM_BYTES = SMEM_FLOATS * 4;   // ~100 KB -> 2 CTAs/SM
}  // namespace cfg

typedef unsigned long long u64;

__device__ __forceinline__ u64 pk2(float x) {
    u64 r; asm("mov.b64 %0, {%1, %1};" : "=l"(r) : "f"(x)); return r;
}
__device__ __forceinline__ void fma2(u64& d, u64 a, u64 b) {
    asm("fma.rn.f32x2 %0, %1, %2, %0;" : "+l"(d) : "l"(a), "l"(b));
}
__device__ __forceinline__ void add2(u64& d, u64 a) {
    asm("add.rn.f32x2 %0, %0, %1;" : "+l"(d) : "l"(a));
}
__device__ __forceinline__ float2 up2(u64 v) {
    float2 r; asm("mov.b64 {%0, %1}, %2;" : "=f"(r.x), "=f"(r.y) : "l"(v)); return r;
}
__device__ __forceinline__ float getp(const u64* a, int r) {
    float2 f = up2(a[r >> 1]); return (r & 1) ? f.y : f.x;
}

// One k-step for 2 columns of ONE batch: a[c][i] += A[i] * w_c
template<int NU>
__device__ __forceinline__ void stepb(u64 a[2][NU], const float* __restrict__ p,
                                      u64 w0, u64 w1) {
    u64 r[NU];
    ulonglong2 t0 = *reinterpret_cast<const ulonglong2*>(p);
    ulonglong2 t1 = *reinterpret_cast<const ulonglong2*>(p + 4);
    r[0] = t0.x; r[1] = t0.y; r[2] = t1.x; r[3] = t1.y;
    if (NU == 5) r[NU - 1] = *reinterpret_cast<const u64*>(p + 8);
    #pragma unroll
    for (int i = 0; i < NU; i++) { fma2(a[0][i], r[i], w0); fma2(a[1][i], r[i], w1); }
}

// ---------------- 2-batch GEMM phases (RG = warp-uniform row group) ----------------

template<int RG>
__device__ __forceinline__ void phaseC2(float* s0, float* s1, int cg, int kh,
                                        const float* __restrict__ ew2,
                                        const float* __restrict__ eb2) {
    using namespace cfg;
    constexpr int NU = RG ? 5 : 4;
    const int r0 = RG * 8, nval = RG ? 9 : 8;
    const int c = cg * 2;
    u64 a[2][2][NU];
    #pragma unroll
    for (int b = 0; b < 2; b++)
        #pragma unroll
        for (int ci = 0; ci < 2; ci++)
            #pragma unroll
            for (int i = 0; i < NU; i++) a[b][ci][i] = 0ull;
    const float* ab0 = s0 + HST_OFF + (kh * 128) * PAD + r0;
    const float* ab1 = s1 + HST_OFF + (kh * 128) * PAD + r0;
    const float* wp = ew2 + (long long)(kh * 128) * D + c;
    #pragma unroll 4
    for (int k = 0; k < 128; k++) {
        float2 w = *reinterpret_cast<const float2*>(wp + (long long)k * D);
        u64 w0 = pk2(w.x), w1 = pk2(w.y);
        stepb<NU>(a[0], ab0 + k * PAD, w0, w1);
        stepb<NU>(a[1], ab1 + k * PAD, w0, w1);
    }
    if (kh) {
        #pragma unroll
        for (int b = 0; b < 2; b++) {
            float* cp = (b ? s1 : s0) + C2P_OFF;
            #pragma unroll
            for (int ci = 0; ci < 2; ci++)
                #pragma unroll
                for (int r = 0; r < nval; r++)
                    cp[(c + ci) * V + r0 + r] = getp(a[b][ci], r);
        }
    }
    __syncthreads();
    if (!kh) {
        #pragma unroll
        for (int b = 0; b < 2; b++) {
            float* s = b ? s1 : s0;
            #pragma unroll
            for (int ci = 0; ci < 2; ci++) {
                const float b2 = eb2[c + ci];
                #pragma unroll
                for (int r = 0; r < nval; r++) {
                    int v = r0 + r;
                    float aa = getp(a[b][ci], r) + s[C2P_OFF + (c + ci) * V + v]
                             + s[DN_OFF + v] * b2;
                    s[AG_OFF + (c + ci) * PAD + v] = aa * s[IV_OFF + v];
                }
            }
        }
    }
}

// Phase D: cpt=4, kh-split (0: h-half, 1: agg-half), in-place merge in H2T.
template<int RG>
__device__ __forceinline__ void phaseD(float* s0, float* s1, int cw, int kh, int lane,
                                       const float* __restrict__ nw1,
                                       const float* __restrict__ nb1) {
    using namespace cfg;
    constexpr int NU = RG ? 5 : 4;
    const int r0 = RG * 8;
    const int c = cw * 128 + lane * 4;
    u64 a0[4][NU], a1[4][NU];
    #pragma unroll
    for (int ci = 0; ci < 4; ci++)
        #pragma unroll
        for (int i = 0; i < NU; i++) { a0[ci][i] = 0ull; a1[ci][i] = 0ull; }
    const float* ab0 = s0 + (kh ? AG_OFF : HT_OFF) + r0;
    const float* ab1 = s1 + (kh ? AG_OFF : HT_OFF) + r0;
    const float* wp = nw1 + (long long)(kh * 128) * H + c;
    #pragma unroll 2
    for (int k = 0; k < 128; k++) {
        u64 r0v[NU], r1v[NU];
        {
            const float* p = ab0 + k * PAD;
            ulonglong2 t0 = *reinterpret_cast<const ulonglong2*>(p);
            ulonglong2 t1 = *reinterpret_cast<const ulonglong2*>(p + 4);
            r0v[0] = t0.x; r0v[1] = t0.y; r0v[2] = t1.x; r0v[3] = t1.y;
            if (NU == 5) r0v[NU - 1] = *reinterpret_cast<const u64*>(p + 8);
        }
        {
            const float* p = ab1 + k * PAD;
            ulonglong2 t0 = *reinterpret_cast<const ulonglong2*>(p);
            ulonglong2 t1 = *reinterpret_cast<const ulonglong2*>(p + 4);
            r1v[0] = t0.x; r1v[1] = t0.y; r1v[2] = t1.x; r1v[3] = t1.y;
            if (NU == 5) r1v[NU - 1] = *reinterpret_cast<const u64*>(p + 8);
        }
        float4 w = *reinterpret_cast<const float4*>(wp + (long long)k * H);
        u64 ww;
        ww = pk2(w.x);
        #pragma unroll
        for (int i = 0; i < NU; i++) { fma2(a0[0][i], r0v[i], ww); fma2(a1[0][i], r1v[i], ww); }
        ww = pk2(w.y);
        #pragma unroll
        for (int i = 0; i < NU; i++) { fma2(a0[1][i], r0v[i], ww); fma2(a1[1][i], r1v[i], ww); }
        ww = pk2(w.z);
        #pragma unroll
        for (int i = 0; i < NU; i++) { fma2(a0[2][i], r0v[i], ww); fma2(a1[2][i], r1v[i], ww); }
        ww = pk2(w.w);
        #pragma unroll
        for (int i = 0; i < NU; i++) { fma2(a0[3][i], r0v[i], ww); fma2(a1[3][i], r1v[i], ww); }
    }
    if (kh) {   // store raw partials (agg-half) into H2T slabs
        #pragma unroll
        for (int ci = 0; ci < 4; ci++) {
            float* d0 = s0 + H2T_OFF + (c + ci) * PAD + r0;
            *reinterpret_cast<ulonglong2*>(d0)     = make_ulonglong2(a0[ci][0], a0[ci][1]);
            *reinterpret_cast<ulonglong2*>(d0 + 4) = make_ulonglong2(a0[ci][2], a0[ci][3]);
            if (RG) *reinterpret_cast<u64*>(d0 + 8) = a0[ci][NU - 1];
            float* d1 = s1 + H2T_OFF + (c + ci) * PAD + r0;
            *reinterpret_cast<ulonglong2*>(d1)     = make_ulonglong2(a1[ci][0], a1[ci][1]);
            *reinterpret_cast<ulonglong2*>(d1 + 4) = make_ulonglong2(a1[ci][2], a1[ci][3]);
            if (RG) *reinterpret_cast<u64*>(d1 + 8) = a1[ci][NU - 1];
        }
    }
    __syncthreads();
    if (!kh) {  // merge + bias + relu, final store
        #pragma unroll
        for (int ci = 0; ci < 4; ci++) {
            const float bb = nb1[c + ci];
            float* d0 = s0 + H2T_OFF + (c + ci) * PAD + r0;
            float* d1 = s1 + H2T_OFF + (c + ci) * PAD + r0;
            {
                ulonglong2 p0 = *reinterpret_cast<const ulonglong2*>(d0);
                ulonglong2 p1 = *reinterpret_cast<const ulonglong2*>(d0 + 4);
                add2(a0[ci][0], p0.x); add2(a0[ci][1], p0.y);
                add2(a0[ci][2], p1.x); add2(a0[ci][3], p1.y);
                if (RG) add2(a0[ci][NU - 1], *reinterpret_cast<const u64*>(d0 + 8));
                #pragma unroll
                for (int j2 = 0; j2 < 4; j2++) {
                    float2 f = up2(a0[ci][j2]);
                    *reinterpret_cast<float2*>(d0 + 2 * j2) =
                        make_float2(fmaxf(f.x + bb, 0.0f), fmaxf(f.y + bb, 0.0f));
                }
                if (RG) {
                    float2 f = up2(a0[ci][NU - 1]);
                    *reinterpret_cast<float2*>(d0 + 8) =
                        make_float2(fmaxf(f.x + bb, 0.0f), 0.0f);
                }
            }
            {
                ulonglong2 p0 = *reinterpret_cast<const ulonglong2*>(d1);
                ulonglong2 p1 = *reinterpret_cast<const ulonglong2*>(d1 + 4);
                add2(a1[ci][0], p0.x); add2(a1[ci][1], p0.y);
                add2(a1[ci][2], p1.x); add2(a1[ci][3], p1.y);
                if (RG) add2(a1[ci][NU - 1], *reinterpret_cast<const u64*>(d1 + 8));
                #pragma unroll
                for (int j2 = 0; j2 < 4; j2++) {
                    float2 f = up2(a1[ci][j2]);
                    *reinterpret_cast<float2*>(d1 + 2 * j2) =
                        make_float2(fmaxf(f.x + bb, 0.0f), fmaxf(f.y + bb, 0.0f));
                }
                if (RG) {
                    float2 f = up2(a1[ci][NU - 1]);
                    *reinterpret_cast<float2*>(d1 + 8) =
                        make_float2(fmaxf(f.x + bb, 0.0f), 0.0f);
                }
            }
        }
    }
}

template<int RG>
__device__ __forceinline__ void phaseE(float* s0, float* s1, int cg, int kh,
                                       const float* __restrict__ nw2,
                                       const float* __restrict__ nb2) {
    using namespace cfg;
    constexpr int NU = RG ? 5 : 4;
    const int r0 = RG * 8, nval = RG ? 9 : 8;
    const int c = cg * 2;
    u64 a[2][2][NU];
    #pragma unroll
    for (int b = 0; b < 2; b++)
        #pragma unroll
        for (int ci = 0; ci < 2; ci++)
            #pragma unroll
            for (int i = 0; i < NU; i++) a[b][ci][i] = 0ull;
    const float* ab0 = s0 + H2T_OFF + (kh * 128) * PAD + r0;
    const float* ab1 = s1 + H2T_OFF + (kh * 128) * PAD + r0;
    const float* wp = nw2 + (long long)(kh * 128) * D + c;
    #pragma unroll 4
    for (int k = 0; k < 128; k++) {
        float2 w = *reinterpret_cast<const float2*>(wp + (long long)k * D);
        u64 w0 = pk2(w.x), w1 = pk2(w.y);
        stepb<NU>(a[0], ab0 + k * PAD, w0, w1);
        stepb<NU>(a[1], ab1 + k * PAD, w0, w1);
    }
    if (kh) {
        #pragma unroll
        for (int b = 0; b < 2; b++) {
            float* ep = (b ? s1 : s0) + EP_OFF;
            #pragma unroll
            for (int ci = 0; ci < 2; ci++)
                #pragma unroll
                for (int r = 0; r < nval; r++)
                    ep[(c + ci) * V + r0 + r] = getp(a[b][ci], r);
        }
    }
    __syncthreads();
    if (!kh) {
        #pragma unroll
        for (int b = 0; b < 2; b++) {
            float* s = b ? s1 : s0;
            #pragma unroll
            for (int ci = 0; ci < 2; ci++) {
                const float b2 = nb2[c + ci];
                #pragma unroll
                for (int r = 0; r < nval; r++) {
                    int v = r0 + r;
                    float delta = getp(a[b][ci], r) + s[EP_OFF + (c + ci) * V + v] + b2;
                    float xv = s[HT_OFF + (c + ci) * PAD + v] + delta * s[HB_OFF + v];
                    s[XB_OFF + v * D + c + ci] = xv;
                }
            }
        }
    }
}

__global__ __launch_bounds__(256, 2) void graph_layer_kernel(
    const float* __restrict__ h, const float* __restrict__ xy,
    const void* __restrict__ jmask_raw, const void* __restrict__ edge_raw,
    const float* __restrict__ ew1, const float* __restrict__ eb1,
    const float* __restrict__ ew2, const float* __restrict__ eb2,
    const float* __restrict__ nw1, const float* __restrict__ nb1,
    const float* __restrict__ nw2, const float* __restrict__ nb2,
    const float* __restrict__ gamma, const float* __restrict__ beta,
    float* __restrict__ out, int nbatch)
{
    using namespace cfg;
    extern __shared__ float sm[];
    int* smi = reinterpret_cast<int*>(sm + INT_OFF);
    __shared__ int s_etype;
    __shared__ int s_mtype;

    const int tid = threadIdx.x;
    const int wrp = tid >> 5, lane = tid & 31;
    const int n0 = blockIdx.x * 2;
    const int nvalid = (nbatch - n0) < 2 ? (nbatch - n0) : 2;

    // ---------------- dtype self-detection ----------------
    if (tid == 0) {
        const unsigned* ew = (const unsigned*)edge_raw;
        unsigned odd_or = 0;
        #pragma unroll
        for (int i = 1; i < 2 * E; i += 2) odd_or |= ew[i];
        s_etype = (odd_or == 0) ? 1 : 0;
        const unsigned* mw = (const unsigned*)jmask_raw;
        bool all_i = true, all_f = true;
        #pragma unroll
        for (int i = 0; i < 64; i++) {
            unsigned w = mw[i];
            all_i = all_i && (w <= 1u);
            all_f = all_f && (w == 0u || w == 0x3F800000u);
        }
        s_mtype = all_i ? 1 : (all_f ? 2 : 0);
    }
    // h transpose + xy per batch
    for (int b = 0; b < nvalid; b++) {
        float* S = sm + b * BSTR;
        const long long nbase = (long long)(n0 + b) * V;
        const float4* h4 = reinterpret_cast<const float4*>(h + nbase * D);
        for (int idx = tid; idx < V * D / 4; idx += 256) {
            int v = (idx * 4) / D, k4 = (idx * 4) % D;
            float4 t = h4[idx];
            S[HT_OFF + (k4 + 0) * PAD + v] = t.x;
            S[HT_OFF + (k4 + 1) * PAD + v] = t.y;
            S[HT_OFF + (k4 + 2) * PAD + v] = t.z;
            S[HT_OFF + (k4 + 3) * PAD + v] = t.w;
        }
        if (tid < D) S[HT_OFF + tid * PAD + 17] = 0.0f;
        if (tid < V) {
            S[SX_OFF + tid] = xy[(nbase + tid) * 2 + 0];
            S[SY_OFF + tid] = xy[(nbase + tid) * 2 + 1];
        }
    }
    if (tid >= 128 && tid < 128 + E) {
        int e = tid - 128;
        const int* e32 = (const int*)edge_raw;
        smi[I_DST + e] = e32[e * 2 + 0];
        smi[I_SRC + e] = e32[e * 2 + 1];
    }
    __syncthreads();

    if (tid < E && s_etype == 1) {
        const long long* e64 = (const long long*)edge_raw;
        smi[I_DST + tid] = (int)e64[tid * 2 + 0];
        smi[I_SRC + tid] = (int)e64[tid * 2 + 1];
    }
    if (tid >= 64 && tid < 64 + 2 * V) {
        int t = tid - 64;
        int b = t / V, v = t - b * V;
        float mf = 0.0f;
        if (b < nvalid) {
            long long idx = (long long)(n0 + b) * V + v;
            if (s_mtype == 0)
                mf = ((const unsigned char*)jmask_raw)[idx] ? 1.0f : 0.0f;
            else if (s_mtype == 1)
                mf = ((const int*)jmask_raw)[idx] ? 1.0f : 0.0f;
            else
                mf = (((const float*)jmask_raw)[idx] != 0.0f) ? 1.0f : 0.0f;
        }
        (sm + b * BSTR)[MF_OFF + v] = mf;
    }
    __syncthreads();

    if (tid < 2 * E) {
        int b = tid >> 5, e = tid & 31;
        float* S = sm + b * BSTR;
        int dv = smi[I_DST + e], sv = smi[I_SRC + e];
        S[RX_OFF + e] = S[SX_OFF + sv] - S[SX_OFF + dv];
        S[RY_OFF + e] = S[SY_OFF + sv] - S[SY_OFF + dv];
        S[VA_OFF + e] = S[MF_OFF + dv] * S[MF_OFF + sv];
    }
    if (tid >= 64 && tid < 64 + V) {
        int v = tid - 64, c = 0;
        #pragma unroll
        for (int e = 0; e < E; e++) c += (smi[I_DST + e] == v);
        smi[I_CNT + v] = c;
    }
    __syncthreads();

    if (tid == 0) {
        int o = 0;
        #pragma unroll
        for (int v = 0; v < V; v++) { smi[I_OFFA + v] = o; o += smi[I_CNT + v]; }
        smi[I_OFFA + V] = o;
    }
    __syncthreads();

    if (tid < 2 * V) {
        int b = tid / V, v = tid - b * V;
        float* S = sm + b * BSTR;
        int pos = smi[I_OFFA + v];
        float dn = 0.0f;
        #pragma unroll
        for (int e = 0; e < E; e++) {
            if (smi[I_DST + e] == v) {
                if (b == 0) smi[I_EORD + pos] = e;
                pos++;
                dn += S[VA_OFF + e];
            }
        }
        S[DN_OFF + v] = dn;
        S[IV_OFF + v] = 1.0f / fmaxf(dn, 1.0f);
        S[HB_OFF + v] = dn > 0.0f ? 1.0f : 0.0f;
    }
    __syncthreads();

    if (tid < 2 * E) {
        int b = tid >> 5, i = tid & 31;
        float* S = sm + b * BSTR;
        int e = smi[I_EORD + i];
        S[SRX_OFF + i] = S[RX_OFF + e];
        S[SRY_OFF + i] = S[RY_OFF + e];
        S[SVA_OFF + i] = S[VA_OFF + e];
        if (b == 0) smi[I_SSRC + i] = smi[I_SRC + e];
    }
    __syncthreads();

    float* s0 = sm;
    float* s1 = sm + BSTR;

    // ------- Phase B (interleaved 2 batches, shared weight loads) + Phase C -------
    {
        const int j = tid;
        u64 aP0[9], aQ0[9], aP1[9], aQ1[9];
        #pragma unroll
        for (int i = 0; i < 9; i++) { aP0[i] = 0ull; aQ0[i] = 0ull; aP1[i] = 0ull; aQ1[i] = 0ull; }
        const float* wPp = ew1 + j;
        const float* wQp = ew1 + (long long)D * H + j;
        #pragma unroll 2
        for (int k = 0; k < D; k++) {
            u64 w0 = pk2(wPp[(long long)k * H]);
            u64 w1 = pk2(wQp[(long long)k * H]);
            const float* r0p = s0 + HT_OFF + k * PAD;
            ulonglong2 t0 = *reinterpret_cast<const ulonglong2*>(r0p);
            ulonglong2 t1 = *reinterpret_cast<const ulonglong2*>(r0p + 4);
            ulonglong2 t2 = *reinterpret_cast<const ulonglong2*>(r0p + 8);
            ulonglong2 t3 = *reinterpret_cast<const ulonglong2*>(r0p + 12);
            u64 t4 = *reinterpret_cast<const u64*>(r0p + 16);
            fma2(aP0[0], t0.x, w0); fma2(aQ0[0], t0.x, w1);
            fma2(aP0[1], t0.y, w0); fma2(aQ0[1], t0.y, w1);
            fma2(aP0[2], t1.x, w0); fma2(aQ0[2], t1.x, w1);
            fma2(aP0[3], t1.y, w0); fma2(aQ0[3], t1.y, w1);
            fma2(aP0[4], t2.x, w0); fma2(aQ0[4], t2.x, w1);
            fma2(aP0[5], t2.y, w0); fma2(aQ0[5], t2.y, w1);
            fma2(aP0[6], t3.x, w0); fma2(aQ0[6], t3.x, w1);
            fma2(aP0[7], t3.y, w0); fma2(aQ0[7], t3.y, w1);
            fma2(aP0[8], t4,   w0); fma2(aQ0[8], t4,   w1);
            const float* r1p = s1 + HT_OFF + k * PAD;
            ulonglong2 u0 = *reinterpret_cast<const ulonglong2*>(r1p);
            ulonglong2 u1 = *reinterpret_cast<const ulonglong2*>(r1p + 4);
            ulonglong2 u2 = *reinterpret_cast<const ulonglong2*>(r1p + 8);
            ulonglong2 u3 = *reinterpret_cast<const ulonglong2*>(r1p + 12);
            u64 u4 = *reinterpret_cast<const u64*>(r1p + 16);
            fma2(aP1[0], u0.x, w0); fma2(aQ1[0], u0.x, w1);
            fma2(aP1[1], u0.y, w0); fma2(aQ1[1], u0.y, w1);
            fma2(aP1[2], u1.x, w0); fma2(aQ1[2], u1.x, w1);
            fma2(aP1[3], u1.y, w0); fma2(aQ1[3], u1.y, w1);
            fma2(aP1[4], u2.x, w0); fma2(aQ1[4], u2.x, w1);
            fma2(aP1[5], u2.y, w0); fma2(aQ1[5], u2.y, w1);
            fma2(aP1[6], u3.x, w0); fma2(aQ1[6], u3.x, w1);
            fma2(aP1[7], u3.y, w0); fma2(aQ1[7], u3.y, w1);
            fma2(aP1[8], u4,   w0); fma2(aQ1[8], u4,   w1);
        }
        // Q -> smem per batch
        #pragma unroll
        for (int i = 0; i < 8; i++) {
            float2 f0 = up2(aQ0[i]);
            s0[Q_OFF + (2 * i) * H + j] = f0.x;
            s0[Q_OFF + (2 * i + 1) * H + j] = f0.y;
            float2 f1 = up2(aQ1[i]);
            s1[Q_OFF + (2 * i) * H + j] = f1.x;
            s1[Q_OFF + (2 * i + 1) * H + j] = f1.y;
        }
        s0[Q_OFF + 16 * H + j] = up2(aQ0[8]).x;
        s1[Q_OFF + 16 * H + j] = up2(aQ1[8]).x;

        // Phase C per batch (P from registers)
        const float b1v = eb1[j];
        const float wx = ew1[(long long)(2 * D) * H + j];
        const float wy = ew1[(long long)(2 * D + 1) * H + j];
        #pragma unroll
        for (int b = 0; b < 2; b++) {
            float* S = b ? s1 : s0;
            const u64* aP = b ? aP1 : aP0;
            float Pv[17];
            #pragma unroll
            for (int i = 0; i < 8; i++) {
                float2 f = up2(aP[i]);
                Pv[2 * i] = f.x; Pv[2 * i + 1] = f.y;
            }
            Pv[16] = up2(aP[8]).x;
            int o0 = smi[I_OFFA + 0];
            #pragma unroll
            for (int v = 0; v < V; v++) {
                const int o1 = smi[I_OFFA + v + 1];
                const float pv = Pv[v];
                float acc = 0.0f;
                for (int i = o0; i < o1; i++) {
                    const int sv = smi[I_SSRC + i];
                    float hid = pv + S[Q_OFF + sv * H + j]
                              + S[SRX_OFF + i] * wx + S[SRY_OFF + i] * wy + b1v;
                    acc = fmaf(fmaxf(hid, 0.0f), S[SVA_OFF + i], acc);
                }
                S[HST_OFF + j * PAD + v] = acc;
                o0 = o1;
            }
        }
    }
    __syncthreads();

    // ------- Phase C2 -------
    {
        const int rgw = wrp & 1;
        const int kh = (wrp >> 1) & 1;
        const int cg = (wrp >> 2) * 32 + lane;
        if (rgw == 0) phaseC2<0>(s0, s1, cg, kh, ew2, eb2);
        else          phaseC2<1>(s0, s1, cg, kh, ew2, eb2);
    }
    __syncthreads();

    // ------- Phase D (cpt=4, kh-split, in-place merge) -------
    {
        const int kh = wrp & 1;
        const int cw = (wrp >> 1) & 1;
        const int rgw = (wrp >> 2) & 1;
        if (rgw == 0) phaseD<0>(s0, s1, cw, kh, lane, nw1, nb1);
        else          phaseD<1>(s0, s1, cw, kh, lane, nw1, nb1);
    }
    __syncthreads();

    // ------- Phase E -------
    {
        const int rgw = wrp & 1;
        const int kh = (wrp >> 1) & 1;
        const int cg = (wrp >> 2) * 32 + lane;
        if (rgw == 0) phaseE<0>(s0, s1, cg, kh, nw2, nb2);
        else          phaseE<1>(s0, s1, cg, kh, nw2, nb2);
    }
    __syncthreads();

    // ------- Phase F: LayerNorm + gamma/beta + mask -------
    {
        const float g0 = gamma[lane], g1 = gamma[lane + 32],
                    g2 = gamma[lane + 64], g3 = gamma[lane + 96];
        const float b0 = beta[lane], b1 = beta[lane + 32],
                    b2 = beta[lane + 64], b3 = beta[lane + 96];
        for (int b = 0; b < nvalid; b++) {
            float* S = sm + b * BSTR;
            const long long nbase = (long long)(n0 + b) * V;
            for (int v = wrp; v < V; v += 8) {
                float x0 = S[XB_OFF + v * D + lane];
                float x1 = S[XB_OFF + v * D + lane + 32];
                float x2 = S[XB_OFF + v * D + lane + 64];
                float x3 = S[XB_OFF + v * D + lane + 96];
                float s = x0 + x1 + x2 + x3;
                #pragma unroll
                for (int off = 16; off > 0; off >>= 1)
                    s += __shfl_xor_sync(0xffffffffu, s, off);
                float mu = s * (1.0f / 128.0f);
                float d0 = x0 - mu, d1 = x1 - mu, d2 = x2 - mu, d3 = x3 - mu;
                float q = d0 * d0 + d1 * d1 + d2 * d2 + d3 * d3;
                #pragma unroll
                for (int off = 16; off > 0; off >>= 1)
                    q += __shfl_xor_sync(0xffffffffu, q, off);
                float rstd = rsqrtf(q * (1.0f / 128.0f) + LN_EPS);
                float m = S[MF_OFF + v];
                long long base = (nbase + v) * D;
                out[base + lane]      = (d0 * rstd * g0 + b0) * m;
                out[base + lane + 32] = (d1 * rstd * g1 + b1) * m;
                out[base + lane + 64] = (d2 * rstd * g2 + b2) * m;
                out[base + lane + 96] = (d3 * rstd * g3 + b3) * m;
            }
        }
    }
}

extern "C" void kernel_launch(void* const* d_in, const int* in_sizes, int n_in,
                              void* d_out, int out_size) {
    using namespace cfg;
    const float* h = (const float*)d_in[0];
    const float* xy = (const float*)d_in[1];
    const void* jmask = d_in[2];
    const void* edge = d_in[3];
    const float* ew1 = (const float*)d_in[4];
    const float* eb1 = (const float*)d_in[5];
    const float* ew2 = (const float*)d_in[6];
    const float* eb2 = (const float*)d_in[7];
    const float* nw1 = (const float*)d_in[8];
    const float* nb1 = (const float*)d_in[9];
    const float* nw2 = (const float*)d_in[10];
    const float* nb2 = (const float*)d_in[11];
    const float* gamma = (const float*)d_in[12];
    const float* beta = (const float*)d_in[13];
    float* out = (float*)d_out;

    const int nbatch = in_sizes[0] / (V * D);
    const int nblk = (nbatch + 1) / 2;

    cudaFuncSetAttribute(graph_layer_kernel,
                         cudaFuncAttributeMaxDynamicSharedMemorySize, SMEM_BYTES);
    graph_layer_kernel<<<nblk, 256, SMEM_BYTES>>>(
        h, xy, jmask, edge, ew1, eb1, ew2, eb2,
        nw1, nb1, nw2, nb2, gamma, beta, out, nbatch);
}

// round 12
// speedup vs baseline: 1.0819x; 1.0819x over previous
#include <cuda_runtime.h>

namespace cfg {
constexpr int V = 17;
constexpr int D = 128;
constexpr int H = 256;
constexpr int E = 32;
constexpr float LN_EPS = 1e-5f;
constexpr int PAD = 20;   // 80B rows, 16B-aligned

// ---- shared memory layout (float offsets) ----
constexpr int HT_OFF  = 0;                 // hT[128][20]          (A..E)
constexpr int R3_OFF  = HT_OFF + D * PAD;  // 2560: hsumT[256][20] (C..C2) / hid2T (D..E) / XB head (E..F)
constexpr int HST_OFF = R3_OFF;
constexpr int H2T_OFF = R3_OFF;
constexpr int XB_OFF  = R3_OFF;            // x[17][128] = 2176 fl (E epilogue, hid2T dead)
constexpr int R2_OFF  = R3_OFF + H * PAD;  // 7680
constexpr int Q_OFF   = R2_OFF;            // Q[17][256] = 4352    (B..C)
constexpr int AG_OFF  = R2_OFF;            // aggT[128][20] = 2560 (C2..D)
constexpr int EP_OFF  = R2_OFF;            // E partials [128][17] = 2176 (E, AG dead)
constexpr int C2P_OFF = R2_OFF + D * PAD;  // 10240: C2 partials [128][17] = 2176
constexpr int R2_END  = C2P_OFF + D * V;   // 12416

constexpr int MISC = R2_END;
constexpr int SX_OFF = MISC;
constexpr int SY_OFF = SX_OFF + V;
constexpr int MF_OFF = SY_OFF + V;
constexpr int IV_OFF = MF_OFF + V;
constexpr int HB_OFF = IV_OFF + V;
constexpr int DN_OFF = HB_OFF + V;
constexpr int RX_OFF = DN_OFF + V;
constexpr int RY_OFF = RX_OFF + E;
constexpr int VA_OFF = RY_OFF + E;
constexpr int SRX_OFF = VA_OFF + E;
constexpr int SRY_OFF = SRX_OFF + E;
constexpr int SVA_OFF = SRY_OFF + E;
constexpr int INT_OFF = SVA_OFF + E;
constexpr int I_DST = 0, I_SRC = 32, I_SSRC = 64, I_EORD = 96, I_CNT = 128, I_OFFA = 145;
constexpr int SMEM_FLOATS = INT_OFF + 163 + 13;
constexpr int SMEM_BYTES = SMEM_FLOATS * 4;   // ~51.5 KB -> 4 CTAs/SM
}  // namespace cfg

typedef unsigned long long u64;

__device__ __forceinline__ u64 pk2(float x) {
    u64 r; asm("mov.b64 %0, {%1, %1};" : "=l"(r) : "f"(x)); return r;
}
__device__ __forceinline__ void fma2(u64& d, u64 a, u64 b) {
    asm("fma.rn.f32x2 %0, %1, %2, %0;" : "+l"(d) : "l"(a), "l"(b));
}
__device__ __forceinline__ void add2(u64& d, u64 a) {
    asm("add.rn.f32x2 %0, %0, %1;" : "+l"(d) : "l"(a));
}
__device__ __forceinline__ float2 up2(u64 v) {
    float2 r; asm("mov.b64 {%0, %1}, %2;" : "=f"(r.x), "=f"(r.y) : "l"(v)); return r;
}

// 2-column accumulator over NU packed row-pairs (NU=4: rows0-7; NU=5: rows8-17, last lane pad)
template<int NU>
struct Acc2 {
    u64 a[2][NU];
    __device__ __forceinline__ void zero() {
        #pragma unroll
        for (int c = 0; c < 2; c++)
            #pragma unroll
            for (int i = 0; i < NU; i++) a[c][i] = 0ull;
    }
    __device__ __forceinline__ void step(const float* __restrict__ p, float2 w) {
        u64 r[NU];
        ulonglong2 t0 = *reinterpret_cast<const ulonglong2*>(p);
        ulonglong2 t1 = *reinterpret_cast<const ulonglong2*>(p + 4);
        r[0] = t0.x; r[1] = t0.y; r[2] = t1.x; r[3] = t1.y;
        if (NU == 5) r[NU - 1] = *reinterpret_cast<const u64*>(p + 8);
        u64 w0 = pk2(w.x), w1 = pk2(w.y);
        #pragma unroll
        for (int i = 0; i < NU; i++) { fma2(a[0][i], r[i], w0); fma2(a[1][i], r[i], w1); }
    }
    __device__ __forceinline__ float get(int c, int r) const {
        float2 f = up2(a[c][r >> 1]); return (r & 1) ? f.y : f.x;
    }
};

// ---------------- templated GEMM phases (RG = warp-uniform row group) ----------------

template<int RG>
__device__ __forceinline__ void phaseC2(float* sm, int cg, int kh,
                                        const float* __restrict__ ew2,
                                        const float* __restrict__ eb2) {
    using namespace cfg;
    constexpr int NU = RG ? 5 : 4;
    const int r0 = RG * 8, nval = RG ? 9 : 8;
    const int c = cg * 2;
    Acc2<NU> t; t.zero();
    const float* ab = sm + HST_OFF + (kh * 128) * PAD + r0;
    const float* wp = ew2 + (long long)(kh * 128) * D + c;
    #pragma unroll 4
    for (int k = 0; k < 128; k++)
        t.step(ab + k * PAD, *reinterpret_cast<const float2*>(wp + (long long)k * D));
    if (kh) {
        #pragma unroll
        for (int ci = 0; ci < 2; ci++)
            #pragma unroll
            for (int r = 0; r < nval; r++)
                sm[C2P_OFF + (c + ci) * V + r0 + r] = t.get(ci, r);
    }
    __syncthreads();
    if (!kh) {
        #pragma unroll
        for (int ci = 0; ci < 2; ci++) {
            const float b2 = eb2[c + ci];
            #pragma unroll
            for (int r = 0; r < nval; r++) {
                int v = r0 + r;
                float a = t.get(ci, r) + sm[C2P_OFF + (c + ci) * V + v]
                        + sm[DN_OFF + v] * b2;
                sm[AG_OFF + (c + ci) * PAD + v] = a * sm[IV_OFF + v];
            }
        }
    }
}

// Phase D: hid2 = relu([h,agg] @ nw1 + nb1).
// 8 warps = kh2 (source half) x cw2 (col half) x RG2 (row group), cpt=4, K=128/warp.
// Partials merged IN-PLACE in H2T: each (col, rg) slab has exactly one kh1 writer
// (raw store) and one kh0 owner (add + bias + relu after the sync).
template<int RG>
__device__ __forceinline__ void phaseD(float* sm, int cw, int kh, int lane,
                                       const float* __restrict__ nw1,
                                       const float* __restrict__ nb1) {
    using namespace cfg;
    constexpr int NU = RG ? 5 : 4;
    const int r0 = RG * 8;
    const int c = cw * 128 + lane * 4;
    u64 acc[4][NU];
    #pragma unroll
    for (int ci = 0; ci < 4; ci++)
        #pragma unroll
        for (int i = 0; i < NU; i++) acc[ci][i] = 0ull;
    const float* ab = sm + (kh ? AG_OFF : HT_OFF) + r0;
    const float* wp = nw1 + (long long)(kh * 128) * H + c;
    #pragma unroll 2
    for (int k = 0; k < 128; k++) {
        u64 r[NU];
        const float* p = ab + k * PAD;
        ulonglong2 t0 = *reinterpret_cast<const ulonglong2*>(p);
        ulonglong2 t1 = *reinterpret_cast<const ulonglong2*>(p + 4);
        r[0] = t0.x; r[1] = t0.y; r[2] = t1.x; r[3] = t1.y;
        if (NU == 5) r[NU - 1] = *reinterpret_cast<const u64*>(p + 8);
        float4 w = *reinterpret_cast<const float4*>(wp + (long long)k * H);
        u64 ww;
        ww = pk2(w.x);
        #pragma unroll
        for (int i = 0; i < NU; i++) fma2(acc[0][i], r[i], ww);
        ww = pk2(w.y);
        #pragma unroll
        for (int i = 0; i < NU; i++) fma2(acc[1][i], r[i], ww);
        ww = pk2(w.z);
        #pragma unroll
        for (int i = 0; i < NU; i++) fma2(acc[2][i], r[i], ww);
        ww = pk2(w.w);
        #pragma unroll
        for (int i = 0; i < NU; i++) fma2(acc[3][i], r[i], ww);
    }
    if (kh) {   // raw partial store (agg-half) into our (col, rg) slab
        #pragma unroll
        for (int ci = 0; ci < 4; ci++) {
            float* d = sm + H2T_OFF + (c + ci) * PAD + r0;
            *reinterpret_cast<ulonglong2*>(d)     = make_ulonglong2(acc[ci][0], acc[ci][1]);
            *reinterpret_cast<ulonglong2*>(d + 4) = make_ulonglong2(acc[ci][2], acc[ci][3]);
            if (RG) *reinterpret_cast<u64*>(d + 8) = acc[ci][NU - 1];
        }
    }
    __syncthreads();
    if (!kh) {  // merge + bias + relu, final store (same slab)
        #pragma unroll
        for (int ci = 0; ci < 4; ci++) {
            float* d = sm + H2T_OFF + (c + ci) * PAD + r0;
            ulonglong2 p0 = *reinterpret_cast<const ulonglong2*>(d);
            ulonglong2 p1 = *reinterpret_cast<const ulonglong2*>(d + 4);
            add2(acc[ci][0], p0.x); add2(acc[ci][1], p0.y);
            add2(acc[ci][2], p1.x); add2(acc[ci][3], p1.y);
            if (RG) add2(acc[ci][NU - 1], *reinterpret_cast<const u64*>(d + 8));
            const float bb = nb1[c + ci];
            #pragma unroll
            for (int j2 = 0; j2 < 4; j2++) {
                float2 f = up2(acc[ci][j2]);
                *reinterpret_cast<float2*>(d + 2 * j2) =
                    make_float2(fmaxf(f.x + bb, 0.0f), fmaxf(f.y + bb, 0.0f));
            }
            if (RG) {
                float2 f = up2(acc[ci][NU - 1]);
                *reinterpret_cast<float2*>(d + 8) =
                    make_float2(fmaxf(f.x + bb, 0.0f), 0.0f);
            }
        }
    }
}

template<int RG>
__device__ __forceinline__ void phaseE(float* sm, int cg, int kh,
                                       const float* __restrict__ nw2,
                                       const float* __restrict__ nb2) {
    using namespace cfg;
    constexpr int NU = RG ? 5 : 4;
    const int r0 = RG * 8, nval = RG ? 9 : 8;
    const int c = cg * 2;
    Acc2<NU> t; t.zero();
    const float* ab = sm + H2T_OFF + (kh * 128) * PAD + r0;
    const float* wp = nw2 + (long long)(kh * 128) * D + c;
    #pragma unroll 4
    for (int k = 0; k < 128; k++)
        t.step(ab + k * PAD, *reinterpret_cast<const float2*>(wp + (long long)k * D));
    if (kh) {
        #pragma unroll
        for (int ci = 0; ci < 2; ci++)
            #pragma unroll
            for (int r = 0; r < nval; r++)
                sm[EP_OFF + (c + ci) * V + r0 + r] = t.get(ci, r);
    }
    __syncthreads();
    if (!kh) {
        #pragma unroll
        for (int ci = 0; ci < 2; ci++) {
            const float b2 = nb2[c + ci];
            #pragma unroll
            for (int r = 0; r < nval; r++) {
                int v = r0 + r;
                float delta = t.get(ci, r) + sm[EP_OFF + (c + ci) * V + v] + b2;
                float xv = sm[HT_OFF + (c + ci) * PAD + v] + delta * sm[HB_OFF + v];
                sm[XB_OFF + v * D + c + ci] = xv;
            }
        }
    }
}

__global__ __launch_bounds__(256, 4) void graph_layer_kernel(
    const float* __restrict__ h, const float* __restrict__ xy,
    const void* __restrict__ jmask_raw, const void* __restrict__ edge_raw,
    const float* __restrict__ ew1, const float* __restrict__ eb1,
    const float* __restrict__ ew2, const float* __restrict__ eb2,
    const float* __restrict__ nw1, const float* __restrict__ nb1,
    const float* __restrict__ nw2, const float* __restrict__ nb2,
    const float* __restrict__ gamma, const float* __restrict__ beta,
    float* __restrict__ out)
{
    using namespace cfg;
    extern __shared__ float sm[];
    int* smi = reinterpret_cast<int*>(sm + INT_OFF);
    __shared__ int s_etype;
    __shared__ int s_mtype;

    const int n = blockIdx.x;
    const int tid = threadIdx.x;
    const int wrp = tid >> 5, lane = tid & 31;
    const long long nbase = (long long)n * V;

    // ---------------- dtype self-detection ----------------
    if (tid == 0) {
        const unsigned* ew = (const unsigned*)edge_raw;
        unsigned odd_or = 0;
        #pragma unroll
        for (int i = 1; i < 2 * E; i += 2) odd_or |= ew[i];
        s_etype = (odd_or == 0) ? 1 : 0;
        const unsigned* mw = (const unsigned*)jmask_raw;
        bool all_i = true, all_f = true;
        #pragma unroll
        for (int i = 0; i < 64; i++) {
            unsigned w = mw[i];
            all_i = all_i && (w <= 1u);
            all_f = all_f && (w == 0u || w == 0x3F800000u);
        }
        s_mtype = all_i ? 1 : (all_f ? 2 : 0);
    }
    // h transpose + zero pad col 17
    {
        const float4* h4 = reinterpret_cast<const float4*>(h + nbase * D);
        for (int idx = tid; idx < V * D / 4; idx += 256) {
            int v = (idx * 4) / D, k4 = (idx * 4) % D;
            float4 t = h4[idx];
            sm[HT_OFF + (k4 + 0) * PAD + v] = t.x;
            sm[HT_OFF + (k4 + 1) * PAD + v] = t.y;
            sm[HT_OFF + (k4 + 2) * PAD + v] = t.z;
            sm[HT_OFF + (k4 + 3) * PAD + v] = t.w;
        }
        if (tid < D) sm[HT_OFF + tid * PAD + 17] = 0.0f;
    }
    if (tid < V) {
        sm[SX_OFF + tid] = xy[(nbase + tid) * 2 + 0];
        sm[SY_OFF + tid] = xy[(nbase + tid) * 2 + 1];
    }
    __syncthreads();

    if (tid < V) {
        float mf;
        if (s_mtype == 0)
            mf = ((const unsigned char*)jmask_raw)[nbase + tid] ? 1.0f : 0.0f;
        else if (s_mtype == 1)
            mf = ((const int*)jmask_raw)[nbase + tid] ? 1.0f : 0.0f;
        else
            mf = (((const float*)jmask_raw)[nbase + tid] != 0.0f) ? 1.0f : 0.0f;
        sm[MF_OFF + tid] = mf;
    }
    if (tid < E) {
        int dv, sv;
        if (s_etype == 1) {
            const long long* e64 = (const long long*)edge_raw;
            dv = (int)e64[tid * 2 + 0];
            sv = (int)e64[tid * 2 + 1];
        } else {
            const int* e32 = (const int*)edge_raw;
            dv = e32[tid * 2 + 0];
            sv = e32[tid * 2 + 1];
        }
        smi[I_DST + tid] = dv;
        smi[I_SRC + tid] = sv;
    }
    __syncthreads();

    if (tid < E) {
        int dv = smi[I_DST + tid], sv = smi[I_SRC + tid];
        sm[RX_OFF + tid] = sm[SX_OFF + sv] - sm[SX_OFF + dv];
        sm[RY_OFF + tid] = sm[SY_OFF + sv] - sm[SY_OFF + dv];
        sm[VA_OFF + tid] = sm[MF_OFF + dv] * sm[MF_OFF + sv];
    }
    if (tid >= 64 && tid < 64 + V) {
        int v = tid - 64, c = 0;
        #pragma unroll
        for (int e = 0; e < E; e++) c += (smi[I_DST + e] == v);
        smi[I_CNT + v] = c;
    }
    __syncthreads();

    if (tid == 0) {
        int o = 0;
        #pragma unroll
        for (int v = 0; v < V; v++) { smi[I_OFFA + v] = o; o += smi[I_CNT + v]; }
        smi[I_OFFA + V] = o;
    }
    __syncthreads();

    if (tid < V) {
        int pos = smi[I_OFFA + tid];
        float dn = 0.0f;
        #pragma unroll
        for (int e = 0; e < E; e++) {
            if (smi[I_DST + e] == tid) {
                smi[I_EORD + pos++] = e;
                dn += sm[VA_OFF + e];
            }
        }
        sm[DN_OFF + tid] = dn;
        sm[IV_OFF + tid] = 1.0f / fmaxf(dn, 1.0f);
        sm[HB_OFF + tid] = dn > 0.0f ? 1.0f : 0.0f;
    }
    __syncthreads();

    if (tid < E) {
        int e = smi[I_EORD + tid];
        smi[I_SSRC + tid] = smi[I_SRC + e];
        sm[SRX_OFF + tid] = sm[RX_OFF + e];
        sm[SRY_OFF + tid] = sm[RY_OFF + e];
        sm[SVA_OFF + tid] = sm[VA_OFF + e];
    }
    __syncthreads();

    // ------- Phase B+C fused: thread j owns column j of P (regs) and Q (smem) -------
    {
        const int j = tid;
        u64 accP[9], accQ[9];
        #pragma unroll
        for (int i = 0; i < 9; i++) { accP[i] = 0ull; accQ[i] = 0ull; }
        const float* wP = ew1 + j;
        const float* wQ = ew1 + (long long)D * H + j;
        #pragma unroll 2
        for (int k = 0; k < D; k++) {
            const float* row = sm + HT_OFF + k * PAD;
            float wpv = wP[(long long)k * H];
            float wqv = wQ[(long long)k * H];
            u64 w0 = pk2(wpv), w1 = pk2(wqv);
            ulonglong2 t0 = *reinterpret_cast<const ulonglong2*>(row);
            ulonglong2 t1 = *reinterpret_cast<const ulonglong2*>(row + 4);
            fma2(accP[0], t0.x, w0); fma2(accQ[0], t0.x, w1);
            fma2(accP[1], t0.y, w0); fma2(accQ[1], t0.y, w1);
            fma2(accP[2], t1.x, w0); fma2(accQ[2], t1.x, w1);
            fma2(accP[3], t1.y, w0); fma2(accQ[3], t1.y, w1);
            ulonglong2 t2 = *reinterpret_cast<const ulonglong2*>(row + 8);
            ulonglong2 t3 = *reinterpret_cast<const ulonglong2*>(row + 12);
            u64 t4 = *reinterpret_cast<const u64*>(row + 16);
            fma2(accP[4], t2.x, w0); fma2(accQ[4], t2.x, w1);
            fma2(accP[5], t2.y, w0); fma2(accQ[5], t2.y, w1);
            fma2(accP[6], t3.x, w0); fma2(accQ[6], t3.x, w1);
            fma2(accP[7], t3.y, w0); fma2(accQ[7], t3.y, w1);
            fma2(accP[8], t4,   w0); fma2(accQ[8], t4,   w1);
        }
        // Q column j -> smem
        #pragma unroll
        for (int i = 0; i < 8; i++) {
            float2 f = up2(accQ[i]);
            sm[Q_OFF + (2 * i) * H + j] = f.x;
            sm[Q_OFF + (2 * i + 1) * H + j] = f.y;
        }
        sm[Q_OFF + 16 * H + j] = up2(accQ[8]).x;

        // ------- Phase C: hsumT[j][v], P from registers -------
        float Pv[17];
        #pragma unroll
        for (int i = 0; i < 8; i++) {
            float2 f = up2(accP[i]);
            Pv[2 * i] = f.x; Pv[2 * i + 1] = f.y;
        }
        Pv[16] = up2(accP[8]).x;

        const float b1v = eb1[j];
        const float wx = ew1[(long long)(2 * D) * H + j];
        const float wy = ew1[(long long)(2 * D + 1) * H + j];
        int o0 = smi[I_OFFA + 0];
        #pragma unroll
        for (int v = 0; v < V; v++) {
            const int o1 = smi[I_OFFA + v + 1];
            const float pv = Pv[v];
            float acc = 0.0f;
            for (int i = o0; i < o1; i++) {
                const int sv = smi[I_SSRC + i];
                float hid = pv + sm[Q_OFF + sv * H + j]
                          + sm[SRX_OFF + i] * wx + sm[SRY_OFF + i] * wy + b1v;
                acc = fmaf(fmaxf(hid, 0.0f), sm[SVA_OFF + i], acc);
            }
            sm[HST_OFF + j * PAD + v] = acc;
            o0 = o1;
        }
        sm[HST_OFF + j * PAD + 17] = 0.0f;   // pad lane for rg1 slab loads
    }
    __syncthreads();

    // ------- Phase C2: agg (warp-uniform rg; cg 0..63; kh 0..1) -------
    {
        const int rgw = wrp & 1;
        const int kh = (wrp >> 1) & 1;
        const int cg = (wrp >> 2) * 32 + lane;
        if (rgw == 0) phaseC2<0>(sm, cg, kh, ew2, eb2);
        else          phaseC2<1>(sm, cg, kh, ew2, eb2);
    }
    __syncthreads();

    // ------- Phase D: kh2 x cw2 x rg2, cpt=4, in-place merge -------
    {
        const int kh = wrp & 1;
        const int cw = (wrp >> 1) & 1;
        const int rgw = (wrp >> 2) & 1;
        if (rgw == 0) phaseD<0>(sm, cw, kh, lane, nw1, nb1);
        else          phaseD<1>(sm, cw, kh, lane, nw1, nb1);
    }
    __syncthreads();

    // ------- Phase E: delta + residual -------
    {
        const int rgw = wrp & 1;
        const int kh = (wrp >> 1) & 1;
        const int cg = (wrp >> 2) * 32 + lane;
        if (rgw == 0) phaseE<0>(sm, cg, kh, nw2, nb2);
        else          phaseE<1>(sm, cg, kh, nw2, nb2);
    }
    __syncthreads();

    // ------- Phase F: LayerNorm + gamma/beta + mask -------
    {
        const float g0 = gamma[lane], g1 = gamma[lane + 32],
                    g2 = gamma[lane + 64], g3 = gamma[lane + 96];
        const float b0 = beta[lane], b1 = beta[lane + 32],
                    b2 = beta[lane + 64], b3 = beta[lane + 96];
        for (int v = wrp; v < V; v += 8) {
            float x0 = sm[XB_OFF + v * D + lane];
            float x1 = sm[XB_OFF + v * D + lane + 32];
            float x2 = sm[XB_OFF + v * D + lane + 64];
            float x3 = sm[XB_OFF + v * D + lane + 96];
            float s = x0 + x1 + x2 + x3;
            #pragma unroll
            for (int off = 16; off > 0; off >>= 1)
                s += __shfl_xor_sync(0xffffffffu, s, off);
            float mu = s * (1.0f / 128.0f);
            float d0 = x0 - mu, d1 = x1 - mu, d2 = x2 - mu, d3 = x3 - mu;
            float q = d0 * d0 + d1 * d1 + d2 * d2 + d3 * d3;
            #pragma unroll
            for (int off = 16; off > 0; off >>= 1)
                q += __shfl_xor_sync(0xffffffffu, q, off);
            float rstd = rsqrtf(q * (1.0f / 128.0f) + LN_EPS);
            float m = sm[MF_OFF + v];
            long long base = (nbase + v) * D;
            out[base + lane]      = (d0 * rstd * g0 + b0) * m;
            out[base + lane + 32] = (d1 * rstd * g1 + b1) * m;
            out[base + lane + 64] = (d2 * rstd * g2 + b2) * m;
            out[base + lane + 96] = (d3 * rstd * g3 + b3) * m;
        }
    }
}

extern "C" void kernel_launch(void* const* d_in, const int* in_sizes, int n_in,
                              void* d_out, int out_size) {
    using namespace cfg;
    const float* h = (const float*)d_in[0];
    const float* xy = (const float*)d_in[1];
    const void* jmask = d_in[2];
    const void* edge = d_in[3];
    const float* ew1 = (const float*)d_in[4];
    const float* eb1 = (const float*)d_in[5];
    const float* ew2 = (const float*)d_in[6];
    const float* eb2 = (const float*)d_in[7];
    const float* nw1 = (const float*)d_in[8];
    const float* nb1 = (const float*)d_in[9];
    const float* nw2 = (const float*)d_in[10];
    const float* nb2 = (const float*)d_in[11];
    const float* gamma = (const float*)d_in[12];
    const float* beta = (const float*)d_in[13];
    float* out = (float*)d_out;

    const int nbatch = in_sizes[0] / (V * D);

    cudaFuncSetAttribute(graph_layer_kernel,
                         cudaFuncAttributeMaxDynamicSharedMemorySize, SMEM_BYTES);
    graph_layer_kernel<<<nbatch, 256, SMEM_BYTES>>>(
        h, xy, jmask, edge, ew1, eb1, ew2, eb2,
        nw1, nb1, nw2, nb2, gamma, beta, out);
}

// round 13
// speedup vs baseline: 1.2307x; 1.1376x over previous
#include <cuda_runtime.h>

namespace cfg {
constexpr int V = 17;
constexpr int D = 128;
constexpr int H = 256;
constexpr int E = 32;
constexpr float LN_EPS = 1e-5f;
constexpr int PAD = 20;   // 80B rows, 16B-aligned

// ---- shared memory layout (float offsets) ----
constexpr int HT_OFF  = 0;                 // hT[128][20]          (A..E)
constexpr int R3_OFF  = HT_OFF + D * PAD;  // 2560: hsumT[256][20] (C..C2) / hid2T (D..E) / XB head (E..F)
constexpr int HST_OFF = R3_OFF;
constexpr int H2T_OFF = R3_OFF;
constexpr int XB_OFF  = R3_OFF;            // x[17][128] = 2176 fl (E epilogue, hid2T dead)
constexpr int R2_OFF  = R3_OFF + H * PAD;  // 7680
constexpr int Q_OFF   = R2_OFF;            // Q[17][256] = 4352    (B..C)
constexpr int AG_OFF  = R2_OFF;            // aggT[128][20] = 2560 (C2..D)
constexpr int EP_OFF  = R2_OFF;            // E partials [128][17] = 2176 (E, AG dead)
constexpr int C2P_OFF = R2_OFF + D * PAD;  // 10240: C2 partials [128][17] = 2176
constexpr int R2_END  = C2P_OFF + D * V;   // 12416

constexpr int MISC = R2_END;
constexpr int SX_OFF = MISC;               // 12416
constexpr int SY_OFF = SX_OFF + V;
constexpr int MF_OFF = SY_OFF + V;
constexpr int IV_OFF = MF_OFF + V;
constexpr int HB_OFF = IV_OFF + V;
constexpr int DN_OFF = HB_OFF + V;
constexpr int RX_OFF = DN_OFF + V;         // 12518
constexpr int RY_OFF = RX_OFF + E;
constexpr int VA_OFF = RY_OFF + E;         // ends 12614
constexpr int SED_OFF = 12616;             // sorted edge float4 (rx,ry,va,0)[32], 16B-aligned
constexpr int INT_OFF = SED_OFF + 4 * E;   // 12744
constexpr int I_DST = 0, I_SRC = 32, I_SSRC = 64, I_EORD = 96, I_CNT = 128, I_OFFA = 145;
constexpr int SMEM_FLOATS = INT_OFF + 163 + 13;
constexpr int SMEM_BYTES = SMEM_FLOATS * 4;   // ~51.7 KB -> 4 CTAs/SM
}  // namespace cfg

typedef unsigned long long u64;

__device__ __forceinline__ u64 pk2(float x) {
    u64 r; asm("mov.b64 %0, {%1, %1};" : "=l"(r) : "f"(x)); return r;
}
__device__ __forceinline__ void fma2(u64& d, u64 a, u64 b) {
    asm("fma.rn.f32x2 %0, %1, %2, %0;" : "+l"(d) : "l"(a), "l"(b));
}
__device__ __forceinline__ float2 up2(u64 v) {
    float2 r; asm("mov.b64 {%0, %1}, %2;" : "=f"(r.x), "=f"(r.y) : "l"(v)); return r;
}

// 2-column accumulator over NU packed row-pairs (NU=4: rows0-7; NU=5: rows8-17, last lane pad)
template<int NU>
struct Acc2 {
    u64 a[2][NU];
    __device__ __forceinline__ void zero() {
        #pragma unroll
        for (int c = 0; c < 2; c++)
            #pragma unroll
            for (int i = 0; i < NU; i++) a[c][i] = 0ull;
    }
    __device__ __forceinline__ void step(const float* __restrict__ p, float2 w) {
        u64 r[NU];
        ulonglong2 t0 = *reinterpret_cast<const ulonglong2*>(p);
        ulonglong2 t1 = *reinterpret_cast<const ulonglong2*>(p + 4);
        r[0] = t0.x; r[1] = t0.y; r[2] = t1.x; r[3] = t1.y;
        if (NU == 5) r[NU - 1] = *reinterpret_cast<const u64*>(p + 8);
        u64 w0 = pk2(w.x), w1 = pk2(w.y);
        #pragma unroll
        for (int i = 0; i < NU; i++) { fma2(a[0][i], r[i], w0); fma2(a[1][i], r[i], w1); }
    }
    __device__ __forceinline__ float get(int c, int r) const {
        float2 f = up2(a[c][r >> 1]); return (r & 1) ? f.y : f.x;
    }
};

// ---------------- templated GEMM phases (RG = warp-uniform row group) ----------------

template<int RG>
__device__ __forceinline__ void phaseC2(float* sm, int cg, int kh,
                                        const float* __restrict__ ew2,
                                        const float* __restrict__ eb2) {
    using namespace cfg;
    constexpr int NU = RG ? 5 : 4;
    const int r0 = RG * 8, nval = RG ? 9 : 8;
    const int c = cg * 2;
    Acc2<NU> t; t.zero();
    const float* ab = sm + HST_OFF + (kh * 128) * PAD + r0;
    const float* wp = ew2 + (long long)(kh * 128) * D + c;
    #pragma unroll 4
    for (int k = 0; k < 128; k++)
        t.step(ab + k * PAD, *reinterpret_cast<const float2*>(wp + (long long)k * D));
    if (kh) {
        #pragma unroll
        for (int ci = 0; ci < 2; ci++)
            #pragma unroll
            for (int r = 0; r < nval; r++)
                sm[C2P_OFF + (c + ci) * V + r0 + r] = t.get(ci, r);
    }
    __syncthreads();
    if (!kh) {
        #pragma unroll
        for (int ci = 0; ci < 2; ci++) {
            const float b2 = eb2[c + ci];
            #pragma unroll
            for (int r = 0; r < nval; r++) {
                int v = r0 + r;
                float a = t.get(ci, r) + sm[C2P_OFF + (c + ci) * V + v]
                        + sm[DN_OFF + v] * b2;
                sm[AG_OFF + (c + ci) * PAD + v] = a * sm[IV_OFF + v];
            }
            if (RG) sm[AG_OFF + (c + ci) * PAD + 17] = 0.0f;
        }
    }
}

template<int RG>
__device__ __forceinline__ void phaseD(float* sm, int cg,
                                       const float* __restrict__ nw1,
                                       const float* __restrict__ nb1) {
    using namespace cfg;
    constexpr int NU = RG ? 5 : 4;
    const int r0 = RG * 8, nval = RG ? 9 : 8;
    const int c = cg * 2;
    Acc2<NU> t; t.zero();
    const float* ab = sm + HT_OFF + r0;
    const float* wp = nw1 + c;
    #pragma unroll 4
    for (int k = 0; k < 128; k++)
        t.step(ab + k * PAD, *reinterpret_cast<const float2*>(wp + (long long)k * H));
    const float* ab2 = sm + AG_OFF + r0;
    const float* wp2 = nw1 + (long long)128 * H + c;
    #pragma unroll 4
    for (int k = 0; k < 128; k++)
        t.step(ab2 + k * PAD, *reinterpret_cast<const float2*>(wp2 + (long long)k * H));
    #pragma unroll
    for (int ci = 0; ci < 2; ci++) {
        const float bb = nb1[c + ci];
        #pragma unroll
        for (int r = 0; r < nval; r++)
            sm[H2T_OFF + (c + ci) * PAD + r0 + r] = fmaxf(t.get(ci, r) + bb, 0.0f);
    }
}

template<int RG>
__device__ __forceinline__ void phaseE(float* sm, int cg, int kh,
                                       const float* __restrict__ nw2,
                                       const float* __restrict__ nb2) {
    using namespace cfg;
    constexpr int NU = RG ? 5 : 4;
    const int r0 = RG * 8, nval = RG ? 9 : 8;
    const int c = cg * 2;
    Acc2<NU> t; t.zero();
    const float* ab = sm + H2T_OFF + (kh * 128) * PAD + r0;
    const float* wp = nw2 + (long long)(kh * 128) * D + c;
    #pragma unroll 4
    for (int k = 0; k < 128; k++)
        t.step(ab + k * PAD, *reinterpret_cast<const float2*>(wp + (long long)k * D));
    if (kh) {
        #pragma unroll
        for (int ci = 0; ci < 2; ci++)
            #pragma unroll
            for (int r = 0; r < nval; r++)
                sm[EP_OFF + (c + ci) * V + r0 + r] = t.get(ci, r);
    }
    __syncthreads();
    if (!kh) {
        #pragma unroll
        for (int ci = 0; ci < 2; ci++) {
            const float b2 = nb2[c + ci];
            #pragma unroll
            for (int r = 0; r < nval; r++) {
                int v = r0 + r;
                float delta = t.get(ci, r) + sm[EP_OFF + (c + ci) * V + v] + b2;
                float xv = sm[HT_OFF + (c + ci) * PAD + v] + delta * sm[HB_OFF + v];
                sm[XB_OFF + v * D + c + ci] = xv;
            }
        }
    }
}

__global__ __launch_bounds__(256, 4) void graph_layer_kernel(
    const float* __restrict__ h, const float* __restrict__ xy,
    const void* __restrict__ jmask_raw, const void* __restrict__ edge_raw,
    const float* __restrict__ ew1, const float* __restrict__ eb1,
    const float* __restrict__ ew2, const float* __restrict__ eb2,
    const float* __restrict__ nw1, const float* __restrict__ nb1,
    const float* __restrict__ nw2, const float* __restrict__ nb2,
    const float* __restrict__ gamma, const float* __restrict__ beta,
    float* __restrict__ out)
{
    using namespace cfg;
    extern __shared__ float sm[];
    int* smi = reinterpret_cast<int*>(sm + INT_OFF);
    __shared__ int s_etype;
    __shared__ int s_mtype;

    const int n = blockIdx.x;
    const int tid = threadIdx.x;
    const int wrp = tid >> 5, lane = tid & 31;
    const long long nbase = (long long)n * V;

    // ---------------- dtype self-detection ----------------
    if (tid == 0) {
        const unsigned* ew = (const unsigned*)edge_raw;
        unsigned odd_or = 0;
        #pragma unroll
        for (int i = 1; i < 2 * E; i += 2) odd_or |= ew[i];
        s_etype = (odd_or == 0) ? 1 : 0;
        const unsigned* mw = (const unsigned*)jmask_raw;
        bool all_i = true, all_f = true;
        #pragma unroll
        for (int i = 0; i < 64; i++) {
            unsigned w = mw[i];
            all_i = all_i && (w <= 1u);
            all_f = all_f && (w == 0u || w == 0x3F800000u);
        }
        s_mtype = all_i ? 1 : (all_f ? 2 : 0);
    }
    // h transpose + zero pad col 17
    {
        const float4* h4 = reinterpret_cast<const float4*>(h + nbase * D);
        for (int idx = tid; idx < V * D / 4; idx += 256) {
            int v = (idx * 4) / D, k4 = (idx * 4) % D;
            float4 t = h4[idx];
            sm[HT_OFF + (k4 + 0) * PAD + v] = t.x;
            sm[HT_OFF + (k4 + 1) * PAD + v] = t.y;
            sm[HT_OFF + (k4 + 2) * PAD + v] = t.z;
            sm[HT_OFF + (k4 + 3) * PAD + v] = t.w;
        }
        if (tid < D) sm[HT_OFF + tid * PAD + 17] = 0.0f;
    }
    if (tid < V) {
        sm[SX_OFF + tid] = xy[(nbase + tid) * 2 + 0];
        sm[SY_OFF + tid] = xy[(nbase + tid) * 2 + 1];
    }
    __syncthreads();

    if (tid < V) {
        float mf;
        if (s_mtype == 0)
            mf = ((const unsigned char*)jmask_raw)[nbase + tid] ? 1.0f : 0.0f;
        else if (s_mtype == 1)
            mf = ((const int*)jmask_raw)[nbase + tid] ? 1.0f : 0.0f;
        else
            mf = (((const float*)jmask_raw)[nbase + tid] != 0.0f) ? 1.0f : 0.0f;
        sm[MF_OFF + tid] = mf;
    }
    if (tid < E) {
        int dv, sv;
        if (s_etype == 1) {
            const long long* e64 = (const long long*)edge_raw;
            dv = (int)e64[tid * 2 + 0];
            sv = (int)e64[tid * 2 + 1];
        } else {
            const int* e32 = (const int*)edge_raw;
            dv = e32[tid * 2 + 0];
            sv = e32[tid * 2 + 1];
        }
        smi[I_DST + tid] = dv;
        smi[I_SRC + tid] = sv;
    }
    __syncthreads();

    if (tid < E) {
        int dv = smi[I_DST + tid], sv = smi[I_SRC + tid];
        sm[RX_OFF + tid] = sm[SX_OFF + sv] - sm[SX_OFF + dv];
        sm[RY_OFF + tid] = sm[SY_OFF + sv] - sm[SY_OFF + dv];
        sm[VA_OFF + tid] = sm[MF_OFF + dv] * sm[MF_OFF + sv];
    }
    if (tid >= 64 && tid < 64 + V) {
        int v = tid - 64, c = 0;
        #pragma unroll
        for (int e = 0; e < E; e++) c += (smi[I_DST + e] == v);
        smi[I_CNT + v] = c;
    }
    __syncthreads();

    if (tid == 0) {
        int o = 0;
        #pragma unroll
        for (int v = 0; v < V; v++) { smi[I_OFFA + v] = o; o += smi[I_CNT + v]; }
        smi[I_OFFA + V] = o;
    }
    __syncthreads();

    if (tid < V) {
        int pos = smi[I_OFFA + tid];
        float dn = 0.0f;
        #pragma unroll
        for (int e = 0; e < E; e++) {
            if (smi[I_DST + e] == tid) {
                smi[I_EORD + pos++] = e;
                dn += sm[VA_OFF + e];
            }
        }
        sm[DN_OFF + tid] = dn;
        sm[IV_OFF + tid] = 1.0f / fmaxf(dn, 1.0f);
        sm[HB_OFF + tid] = dn > 0.0f ? 1.0f : 0.0f;
    }
    __syncthreads();

    if (tid < E) {
        int e = smi[I_EORD + tid];
        smi[I_SSRC + tid] = smi[I_SRC + e];
        *reinterpret_cast<float4*>(&sm[SED_OFF + 4 * tid]) =
            make_float4(sm[RX_OFF + e], sm[RY_OFF + e], sm[VA_OFF + e], 0.0f);
    }
    __syncthreads();

    // ------- Phase B+C fused: thread j owns column j of P (regs) and Q (smem) -------
    {
        const int j = tid;
        u64 accP[9], accQ[9];
        #pragma unroll
        for (int i = 0; i < 9; i++) { accP[i] = 0ull; accQ[i] = 0ull; }
        const float* wP = ew1 + j;
        const float* wQ = ew1 + (long long)D * H + j;
        #pragma unroll 2
        for (int k = 0; k < D; k++) {
            const float* row = sm + HT_OFF + k * PAD;
            float wpv = wP[(long long)k * H];
            float wqv = wQ[(long long)k * H];
            u64 w0 = pk2(wpv), w1 = pk2(wqv);
            ulonglong2 t0 = *reinterpret_cast<const ulonglong2*>(row);
            ulonglong2 t1 = *reinterpret_cast<const ulonglong2*>(row + 4);
            fma2(accP[0], t0.x, w0); fma2(accQ[0], t0.x, w1);
            fma2(accP[1], t0.y, w0); fma2(accQ[1], t0.y, w1);
            fma2(accP[2], t1.x, w0); fma2(accQ[2], t1.x, w1);
            fma2(accP[3], t1.y, w0); fma2(accQ[3], t1.y, w1);
            ulonglong2 t2 = *reinterpret_cast<const ulonglong2*>(row + 8);
            ulonglong2 t3 = *reinterpret_cast<const ulonglong2*>(row + 12);
            u64 t4 = *reinterpret_cast<const u64*>(row + 16);
            fma2(accP[4], t2.x, w0); fma2(accQ[4], t2.x, w1);
            fma2(accP[5], t2.y, w0); fma2(accQ[5], t2.y, w1);
            fma2(accP[6], t3.x, w0); fma2(accQ[6], t3.x, w1);
            fma2(accP[7], t3.y, w0); fma2(accQ[7], t3.y, w1);
            fma2(accP[8], t4,   w0); fma2(accQ[8], t4,   w1);
        }
        // Q column j -> smem
        #pragma unroll
        for (int i = 0; i < 8; i++) {
            float2 f = up2(accQ[i]);
            sm[Q_OFF + (2 * i) * H + j] = f.x;
            sm[Q_OFF + (2 * i + 1) * H + j] = f.y;
        }
        sm[Q_OFF + 16 * H + j] = up2(accQ[8]).x;

        // ------- Phase C: hsumT[j][v], P from registers -------
        float Pv[17];
        #pragma unroll
        for (int i = 0; i < 8; i++) {
            float2 f = up2(accP[i]);
            Pv[2 * i] = f.x; Pv[2 * i + 1] = f.y;
        }
        Pv[16] = up2(accP[8]).x;

        const float b1v = eb1[j];
        const float wx = ew1[(long long)(2 * D) * H + j];
        const float wy = ew1[(long long)(2 * D + 1) * H + j];
        int o0 = smi[I_OFFA + 0];
        #pragma unroll
        for (int v = 0; v < V; v++) {
            const int o1 = smi[I_OFFA + v + 1];
            const float pv = Pv[v];
            float acc = 0.0f;
            for (int i = o0; i < o1; i++) {
                const int sv = smi[I_SSRC + i];
                float4 ed = *reinterpret_cast<const float4*>(&sm[SED_OFF + 4 * i]);
                float hid = pv + sm[Q_OFF + sv * H + j]
                          + ed.x * wx + ed.y * wy + b1v;
                acc = fmaf(fmaxf(hid, 0.0f), ed.z, acc);
            }
            sm[HST_OFF + j * PAD + v] = acc;
            o0 = o1;
        }
        sm[HST_OFF + j * PAD + 17] = 0.0f;   // pad lane for rg1 slab loads
    }
    __syncthreads();

    // ------- Phase C2: agg (warp-uniform rg; cg 0..63; kh 0..1) -------
    {
        const int rgw = wrp & 1;
        const int kh = (wrp >> 1) & 1;
        const int cg = (wrp >> 2) * 32 + lane;
        if (rgw == 0) phaseC2<0>(sm, cg, kh, ew2, eb2);
        else          phaseC2<1>(sm, cg, kh, ew2, eb2);
    }
    __syncthreads();

    // ------- Phase D: hid2 (full K=256 per thread; cg 0..127) -------
    {
        const int rgw = wrp & 1;
        const int cg = (wrp >> 1) * 32 + lane;
        if (rgw == 0) phaseD<0>(sm, cg, nw1, nb1);
        else          phaseD<1>(sm, cg, nw1, nb1);
    }
    __syncthreads();

    // ------- Phase E: delta + residual -------
    {
        const int rgw = wrp & 1;
        const int kh = (wrp >> 1) & 1;
        const int cg = (wrp >> 2) * 32 + lane;
        if (rgw == 0) phaseE<0>(sm, cg, kh, nw2, nb2);
        else          phaseE<1>(sm, cg, kh, nw2, nb2);
    }
    __syncthreads();

    // ------- Phase F: LayerNorm + gamma/beta + mask (vectorized float4) -------
    {
        const float4 g4 = *reinterpret_cast<const float4*>(gamma + lane * 4);
        const float4 b4 = *reinterpret_cast<const float4*>(beta + lane * 4);
        for (int v = wrp; v < V; v += 8) {
            float4 x = *reinterpret_cast<const float4*>(&sm[XB_OFF + v * D + lane * 4]);
            float s = x.x + x.y + x.z + x.w;
            #pragma unroll
            for (int off = 16; off > 0; off >>= 1)
                s += __shfl_xor_sync(0xffffffffu, s, off);
            float mu = s * (1.0f / 128.0f);
            float d0 = x.x - mu, d1 = x.y - mu, d2 = x.z - mu, d3 = x.w - mu;
            float q = d0 * d0 + d1 * d1 + d2 * d2 + d3 * d3;
            #pragma unroll
            for (int off = 16; off > 0; off >>= 1)
                q += __shfl_xor_sync(0xffffffffu, q, off);
            float rstd = rsqrtf(q * (1.0f / 128.0f) + LN_EPS);
            float m = sm[MF_OFF + v];
            float4 o;
            o.x = (d0 * rstd * g4.x + b4.x) * m;
            o.y = (d1 * rstd * g4.y + b4.y) * m;
            o.z = (d2 * rstd * g4.z + b4.z) * m;
            o.w = (d3 * rstd * g4.w + b4.w) * m;
            *reinterpret_cast<float4*>(&out[(nbase + v) * D + lane * 4]) = o;
        }
    }
}

extern "C" void kernel_launch(void* const* d_in, const int* in_sizes, int n_in,
                              void* d_out, int out_size) {
    using namespace cfg;
    const float* h = (const float*)d_in[0];
    const float* xy = (const float*)d_in[1];
    const void* jmask = d_in[2];
    const void* edge = d_in[3];
    const float* ew1 = (const float*)d_in[4];
    const float* eb1 = (const float*)d_in[5];
    const float* ew2 = (const float*)d_in[6];
    const float* eb2 = (const float*)d_in[7];
    const float* nw1 = (const float*)d_in[8];
    const float* nb1 = (const float*)d_in[9];
    const float* nw2 = (const float*)d_in[10];
    const float* nb2 = (const float*)d_in[11];
    const float* gamma = (const float*)d_in[12];
    const float* beta = (const float*)d_in[13];
    float* out = (float*)d_out;

    const int nbatch = in_sizes[0] / (V * D);

    cudaFuncSetAttribute(graph_layer_kernel,
                         cudaFuncAttributeMaxDynamicSharedMemorySize, SMEM_BYTES);
    graph_layer_kernel<<<nbatch, 256, SMEM_BYTES>>>(
        h, xy, jmask, edge, ew1, eb1, ew2, eb2,
        nw1, nb1, nw2, nb2, gamma, beta, out);
}